// round 4
// baseline (speedup 1.0000x reference)
#include <cuda_runtime.h>
#include <cstdint>

#define NN 50000
#define EE 400000
#define DD 256
#define GG 64
#define DOUT 16

// ---------------- static scratch ----------------
__device__ float g_S0[NN * DD];       // tmp = in @ W
__device__ float g_S1[NN * DD];       // layer output
__device__ int   g_degi[NN];
__device__ float g_dinv[NN];
__device__ int   g_rowptr[NN + 1];
__device__ int   g_cursor[NN];
__device__ int   g_csr_src[EE];
__device__ float g_csr_w[EE];
__device__ float g_pool[GG * DD];
__device__ float g_cnt[GG];
__device__ int   g_flags[2];          // [0]: edge_index is32, [1]: batch is32

// ---------------- index dtype ----------------
__device__ __forceinline__ long long fetch_idx(const void* p, long long i, int is32) {
    if (is32) return (long long)((const int*)p)[i];
    return ((const long long*)p)[i];
}

// launch 1: zero everything
__global__ void k_zero() {
    int i = blockIdx.x * blockDim.x + threadIdx.x;
    if (i < NN) g_degi[i] = 0;
    if (i < GG * DD) g_pool[i] = 0.f;
    if (i < GG) g_cnt[i] = 0.f;
    if (i < 2) g_flags[i] = 0;
}

// launch 2: dtype detect for both index buffers.
// int64 values < 2^31 have zero high words; int32 buffers have nonzero odd words.
__global__ void k_detect2(const unsigned* __restrict__ ei, long long ei_words,
                          const unsigned* __restrict__ bt, long long bt_words) {
    long long i = 2ll * ((long long)blockIdx.x * blockDim.x + threadIdx.x) + 1;
    unsigned v0 = (i < ei_words) ? ei[i] : 0u;
    unsigned v1 = (i < bt_words) ? bt[i] : 0u;
#pragma unroll
    for (int o = 16; o > 0; o >>= 1) {
        v0 |= __shfl_xor_sync(0xffffffffu, v0, o);
        v1 |= __shfl_xor_sync(0xffffffffu, v1, o);
    }
    if ((threadIdx.x & 31) == 0) {
        if (v0) atomicOr(&g_flags[0], 1);
        if (v1) atomicOr(&g_flags[1], 1);
    }
}

// launch 3: in-degree histogram
__global__ void k_count(const void* __restrict__ ei, long long E) {
    long long e = (long long)blockIdx.x * blockDim.x + threadIdx.x;
    if (e >= E) return;
    int is32 = g_flags[0];
    long long d = fetch_idx(ei, E + e, is32);
    atomicAdd(&g_degi[d], 1);
}

// launch 5: single-block scan over degrees -> row_ptr + cursor; also dinv
__global__ void k_scan_dinv() {
    __shared__ int part[1024];
    const int CH = (NN + 1023) / 1024;   // 49
    int t = threadIdx.x;
    int beg = t * CH, end = min(beg + CH, NN);
    int s = 0;
    for (int i = beg; i < end; i++) {
        int d = g_degi[i];
        g_dinv[i] = rsqrtf((float)d + 1.0f);   // +1 self loop
        s += d;
    }
    part[t] = s;
    __syncthreads();
    for (int off = 1; off < 1024; off <<= 1) {
        int v = (t >= off) ? part[t - off] : 0;
        __syncthreads();
        part[t] += v;
        __syncthreads();
    }
    int excl = (t == 0) ? 0 : part[t - 1];
    for (int i = beg; i < end; i++) {
        g_rowptr[i] = excl;
        g_cursor[i] = excl;
        excl += g_degi[i];
    }
    if (t == 1023) g_rowptr[NN] = part[1023];
}

// launch 6: CSR fill
__global__ void k_fill(const void* __restrict__ ei, long long E) {
    long long e = (long long)blockIdx.x * blockDim.x + threadIdx.x;
    if (e >= E) return;
    int is32 = g_flags[0];
    int s = (int)fetch_idx(ei, e, is32);
    int d = (int)fetch_idx(ei, E + e, is32);
    int pos = atomicAdd(&g_cursor[d], 1);
    g_csr_src[pos] = s;
    g_csr_w[pos] = g_dinv[s] * g_dinv[d];
}

// ---------------- 3xTF32 tensor-core GEMM (double-buffered) ----------------
// C[M,256] = A[M,256] @ B[256,256]. Block: 128 rows x 256 cols, 8 warps (2m x 4n),
// warp tile 64x64, BK=8. Operands pre-split to tf32 hi/lo during smem staging.
__device__ __forceinline__ void split_tf32(float x, uint32_t& hi, uint32_t& lo) {
    asm("cvt.rna.tf32.f32 %0, %1;" : "=r"(hi) : "f"(x));
    float r = x - __uint_as_float(hi);
    asm("cvt.rna.tf32.f32 %0, %1;" : "=r"(lo) : "f"(r));
}

__device__ __forceinline__ void mma8(float* c, const uint32_t* a, const uint32_t* b) {
    asm volatile(
        "mma.sync.aligned.m16n8k8.row.col.f32.tf32.tf32.f32 "
        "{%0,%1,%2,%3}, {%4,%5,%6,%7}, {%8,%9}, {%0,%1,%2,%3};"
        : "+f"(c[0]), "+f"(c[1]), "+f"(c[2]), "+f"(c[3])
        : "r"(a[0]), "r"(a[1]), "r"(a[2]), "r"(a[3]), "r"(b[0]), "r"(b[1]));
}

#define APAD 12    // As row stride (words): banks (12g+t)%32 all distinct
#define BPAD 264   // Bs row stride (words): 264%32==8 -> banks (8t+g)%32 distinct
#define A_WORDS (2 * 2 * 128 * APAD)                  // 6144
#define B_WORDS (2 * 2 * 8 * BPAD)                    // 8448
#define GEMM_SMEM ((A_WORDS + B_WORDS) * 4)           // 58368 bytes

#define AS(b, h, r, k) sA[((((b) * 2 + (h)) * 128 + (r)) * APAD) + (k)]
#define BS(b, h, k, n) sB[((((b) * 2 + (h)) * 8 + (k)) * BPAD) + (n)]

__global__ __launch_bounds__(256, 1) void k_gemm2(const float* __restrict__ A,
                                                  const float* __restrict__ B,
                                                  float* __restrict__ C, int M) {
    extern __shared__ uint32_t smem_dyn[];
    uint32_t* sA = smem_dyn;
    uint32_t* sB = smem_dyn + A_WORDS;

    int tid = threadIdx.x, wid = tid >> 5, lane = tid & 31;
    int g = lane >> 2, t = lane & 3;
    int wm = wid & 1, wn = wid >> 1;       // warp grid 2(m) x 4(n)
    int bm = blockIdx.x * 128;

    // staging thread mapping
    int a_row = tid >> 1;                  // 0..127
    int a_kk  = (tid & 1) * 4;             // 0 or 4
    int b_k   = tid >> 5;                  // 0..7
    int b_n   = lane * 4;                  // 0..124 (+128 second vec)

    long long a_base = (long long)(bm + a_row) * DD + a_kk;
    bool a_ok = (bm + a_row) < M;
    const float4 z4 = make_float4(0.f, 0.f, 0.f, 0.f);

    float acc[4][8][4];
#pragma unroll
    for (int i = 0; i < 4; i++)
#pragma unroll
        for (int j = 0; j < 8; j++)
#pragma unroll
            for (int q = 0; q < 4; q++) acc[i][j][q] = 0.f;

    // prologue: stage slab 0 into buffer 0
    {
        float4 pa  = a_ok ? *(const float4*)(A + a_base) : z4;
        float4 pb0 = *(const float4*)(B + (long long)b_k * DD + b_n);
        float4 pb1 = *(const float4*)(B + (long long)b_k * DD + b_n + 128);
        uint4 h, l;
        split_tf32(pa.x, h.x, l.x); split_tf32(pa.y, h.y, l.y);
        split_tf32(pa.z, h.z, l.z); split_tf32(pa.w, h.w, l.w);
        *(uint4*)&AS(0, 0, a_row, a_kk) = h;
        *(uint4*)&AS(0, 1, a_row, a_kk) = l;
        split_tf32(pb0.x, h.x, l.x); split_tf32(pb0.y, h.y, l.y);
        split_tf32(pb0.z, h.z, l.z); split_tf32(pb0.w, h.w, l.w);
        *(uint4*)&BS(0, 0, b_k, b_n) = h;
        *(uint4*)&BS(0, 1, b_k, b_n) = l;
        split_tf32(pb1.x, h.x, l.x); split_tf32(pb1.y, h.y, l.y);
        split_tf32(pb1.z, h.z, l.z); split_tf32(pb1.w, h.w, l.w);
        *(uint4*)&BS(0, 0, b_k, b_n + 128) = h;
        *(uint4*)&BS(0, 1, b_k, b_n + 128) = l;
    }
    __syncthreads();

    for (int k0 = 0; k0 < DD / 8; k0++) {
        int cur = k0 & 1, nxt = cur ^ 1;
        bool more = (k0 + 1) < DD / 8;

        // prefetch next slab (LDG issued before compute; consumed after)
        float4 pa = z4, pb0 = z4, pb1 = z4;
        if (more) {
            int kb = (k0 + 1) * 8;
            pa  = a_ok ? *(const float4*)(A + a_base + kb) : z4;
            pb0 = *(const float4*)(B + (long long)(kb + b_k) * DD + b_n);
            pb1 = *(const float4*)(B + (long long)(kb + b_k) * DD + b_n + 128);
        }

        // B fragments once per warp, reused across 4 m-subtiles
        uint32_t bh[8][2], bl[8][2];
#pragma unroll
        for (int j = 0; j < 8; j++) {
            int n = wn * 64 + 8 * j + g;
            bh[j][0] = BS(cur, 0, t, n);     bh[j][1] = BS(cur, 0, t + 4, n);
            bl[j][0] = BS(cur, 1, t, n);     bl[j][1] = BS(cur, 1, t + 4, n);
        }
#pragma unroll
        for (int i = 0; i < 4; i++) {
            int r = wm * 64 + i * 16;
            uint32_t ah[4], al[4];
            ah[0] = AS(cur, 0, r + g, t);      ah[1] = AS(cur, 0, r + g + 8, t);
            ah[2] = AS(cur, 0, r + g, t + 4);  ah[3] = AS(cur, 0, r + g + 8, t + 4);
            al[0] = AS(cur, 1, r + g, t);      al[1] = AS(cur, 1, r + g + 8, t);
            al[2] = AS(cur, 1, r + g, t + 4);  al[3] = AS(cur, 1, r + g + 8, t + 4);
#pragma unroll
            for (int j = 0; j < 8; j++) {
                mma8(acc[i][j], ah, bh[j]);
                mma8(acc[i][j], ah, bl[j]);
                mma8(acc[i][j], al, bh[j]);
            }
        }

        // stage next slab into the other buffer (overlaps nothing being read)
        if (more) {
            uint4 h, l;
            split_tf32(pa.x, h.x, l.x); split_tf32(pa.y, h.y, l.y);
            split_tf32(pa.z, h.z, l.z); split_tf32(pa.w, h.w, l.w);
            *(uint4*)&AS(nxt, 0, a_row, a_kk) = h;
            *(uint4*)&AS(nxt, 1, a_row, a_kk) = l;
            split_tf32(pb0.x, h.x, l.x); split_tf32(pb0.y, h.y, l.y);
            split_tf32(pb0.z, h.z, l.z); split_tf32(pb0.w, h.w, l.w);
            *(uint4*)&BS(nxt, 0, b_k, b_n) = h;
            *(uint4*)&BS(nxt, 1, b_k, b_n) = l;
            split_tf32(pb1.x, h.x, l.x); split_tf32(pb1.y, h.y, l.y);
            split_tf32(pb1.z, h.z, l.z); split_tf32(pb1.w, h.w, l.w);
            *(uint4*)&BS(nxt, 0, b_k, b_n + 128) = h;
            *(uint4*)&BS(nxt, 1, b_k, b_n + 128) = l;
        }
        __syncthreads();
    }

#pragma unroll
    for (int i = 0; i < 4; i++)
#pragma unroll
        for (int j = 0; j < 8; j++) {
            int row0 = bm + wm * 64 + i * 16 + g;
            int col  = wn * 64 + 8 * j + 2 * t;
            if (row0 < M) {
                float2 v = {acc[i][j][0], acc[i][j][1]};
                *(float2*)(C + (long long)row0 * DD + col) = v;
            }
            int row1 = row0 + 8;
            if (row1 < M) {
                float2 v = {acc[i][j][2], acc[i][j][3]};
                *(float2*)(C + (long long)row1 * DD + col) = v;
            }
        }
}

// ---------------- fused aggregate: self-loop + CSR gather + bias + relu --------
__global__ __launch_bounds__(256) void k_aggregate(const float* __restrict__ tmp,
                                                   float* __restrict__ out,
                                                   const float* __restrict__ bias) {
    int node = (int)(((long long)blockIdx.x * blockDim.x + threadIdx.x) >> 5);
    int lane = threadIdx.x & 31;
    if (node >= NN) return;

    float di = g_dinv[node];
    float ws = di * di;
    const float4* r = (const float4*)(tmp + (long long)node * DD);
    float4 v0 = r[lane], v1 = r[lane + 32];
    float4 a0 = {v0.x * ws, v0.y * ws, v0.z * ws, v0.w * ws};
    float4 a1 = {v1.x * ws, v1.y * ws, v1.z * ws, v1.w * ws};

    int p = g_rowptr[node], pe = g_rowptr[node + 1];
    for (; p < pe; ++p) {
        int s = g_csr_src[p];
        float w = g_csr_w[p];
        const float4* rs = (const float4*)(tmp + (long long)s * DD);
        float4 u0 = rs[lane], u1 = rs[lane + 32];
        a0.x += w * u0.x; a0.y += w * u0.y; a0.z += w * u0.z; a0.w += w * u0.w;
        a1.x += w * u1.x; a1.y += w * u1.y; a1.z += w * u1.z; a1.w += w * u1.w;
    }

    float4 b0 = ((const float4*)bias)[lane];
    float4 b1 = ((const float4*)bias)[lane + 32];
    a0.x = fmaxf(a0.x + b0.x, 0.f); a0.y = fmaxf(a0.y + b0.y, 0.f);
    a0.z = fmaxf(a0.z + b0.z, 0.f); a0.w = fmaxf(a0.w + b0.w, 0.f);
    a1.x = fmaxf(a1.x + b1.x, 0.f); a1.y = fmaxf(a1.y + b1.y, 0.f);
    a1.z = fmaxf(a1.z + b1.z, 0.f); a1.w = fmaxf(a1.w + b1.w, 0.f);

    float4* o = (float4*)(out + (long long)node * DD);
    o[lane] = a0;
    o[lane + 32] = a1;
}

// ---------------- pool: batch is sorted -> segmented per-block sums ------------
__global__ void k_pool2(const float* __restrict__ h, const void* __restrict__ batch) {
    int col = threadIdx.x;            // 256 threads = 256 cols
    int n0 = blockIdx.x * 128;
    int n1 = min(n0 + 128, NN);
    int is32 = g_flags[1];
    int cur = (int)fetch_idx(batch, n0, is32);
    float acc = 0.f;
    int cnt = 0;
    for (int n = n0; n < n1; n++) {
        int gid = (int)fetch_idx(batch, n, is32);
        if (gid != cur) {
            atomicAdd(&g_pool[cur * DD + col], acc);
            if (col == 0) atomicAdd(&g_cnt[cur], (float)cnt);
            acc = 0.f; cnt = 0; cur = gid;
        }
        acc += h[(long long)n * DD + col];
        cnt++;
    }
    atomicAdd(&g_pool[cur * DD + col], acc);
    if (col == 0) atomicAdd(&g_cnt[cur], (float)cnt);
}

__global__ void k_fc(const float* __restrict__ Wfc, const float* __restrict__ bfc,
                     float* __restrict__ out) {
    int tt = blockIdx.x * blockDim.x + threadIdx.x;
    if (tt >= GG * DOUT) return;
    int g = tt >> 4, o = tt & 15;
    float inv = 1.0f / fmaxf(g_cnt[g], 1.0f);
    float acc = 0.f;
#pragma unroll 8
    for (int k = 0; k < DD; k++) acc += g_pool[g * DD + k] * Wfc[k * DOUT + o];
    out[tt] = acc * inv + bfc[o];
}

// ---------------- launch ----------------
extern "C" void kernel_launch(void* const* d_in, const int* in_sizes, int n_in,
                              void* d_out, int out_size) {
    const float* x     = (const float*)d_in[0];
    const void*  ei    = d_in[1];
    const void*  batch = d_in[2];
    const float* W1 = (const float*)d_in[3];  const float* b1 = (const float*)d_in[4];
    const float* W2 = (const float*)d_in[5];  const float* b2 = (const float*)d_in[6];
    const float* W3 = (const float*)d_in[7];  const float* b3 = (const float*)d_in[8];
    const float* Wfc = (const float*)d_in[9]; const float* bfc = (const float*)d_in[10];
    float* out = (float*)d_out;

    long long E = in_sizes[1] / 2;

    float *S0, *S1;
    cudaGetSymbolAddress((void**)&S0, g_S0);
    cudaGetSymbolAddress((void**)&S1, g_S1);

    cudaFuncSetAttribute(k_gemm2, cudaFuncAttributeMaxDynamicSharedMemorySize,
                         GEMM_SMEM);

    int gemm_blocks = (NN + 127) / 128;    // 391
    const float* bs[3] = {b1, b2, b3};

    // launch order: GEMM is launch #4 -> gets the ncu -s window
    k_zero<<<(NN + 255) / 256, 256>>>();                                       // 1
    k_detect2<<<(int)((in_sizes[1] / 2 + 255) / 256), 256>>>(
        (const unsigned*)ei, (long long)in_sizes[1],
        (const unsigned*)batch, (long long)in_sizes[2]);                       // 2
    k_count<<<(int)((E + 255) / 256), 256>>>(ei, E);                           // 3
    k_gemm2<<<gemm_blocks, 256, GEMM_SMEM>>>(x, W1, S0, NN);                   // 4 (profiled)
    k_scan_dinv<<<1, 1024>>>();                                                // 5
    k_fill<<<(int)((E + 255) / 256), 256>>>(ei, E);                            // 6
    k_aggregate<<<(NN * 32 + 255) / 256, 256>>>(S0, S1, bs[0]);                // 7

    const float* in = S1;
    const float* Ws23[2] = {W2, W3};
    for (int l = 0; l < 2; l++) {
        k_gemm2<<<gemm_blocks, 256, GEMM_SMEM>>>(in, Ws23[l], S0, NN);
        k_aggregate<<<(NN * 32 + 255) / 256, 256>>>(S0, S1, bs[l + 1]);
        in = S1;
    }

    k_pool2<<<(NN + 127) / 128, 256>>>(S1, batch);
    k_fc<<<(GG * DOUT + 255) / 256, 256>>>(Wfc, bfc, out);
}

// round 5
// speedup vs baseline: 1.0276x; 1.0276x over previous
#include <cuda_runtime.h>
#include <cstdint>

#define NN 50000
#define EE 400000
#define DD 256
#define GG 64
#define DOUT 16

// ---------------- static scratch ----------------
__device__ float g_S0[NN * DD];       // tmp = in @ W
__device__ float g_S1[NN * DD];       // layer output
__device__ int   g_degi[NN];
__device__ float g_dinv[NN];
__device__ int   g_rowptr[NN + 1];
__device__ int   g_cursor[NN];
__device__ int   g_csr_src[EE];
__device__ float g_csr_w[EE];
__device__ float g_pool[GG * DD];
__device__ float g_cnt[GG];
__device__ int   g_flags[2];          // [0]: edge_index is32, [1]: batch is32

// ---------------- index dtype ----------------
__device__ __forceinline__ long long fetch_idx(const void* p, long long i, int is32) {
    if (is32) return (long long)((const int*)p)[i];
    return ((const long long*)p)[i];
}

// launch 1: zero everything
__global__ void k_zero() {
    int i = blockIdx.x * blockDim.x + threadIdx.x;
    if (i < NN) g_degi[i] = 0;
    if (i < GG * DD) g_pool[i] = 0.f;
    if (i < GG) g_cnt[i] = 0.f;
    if (i < 2) g_flags[i] = 0;
}

// launch 2: dtype detect for both index buffers.
__global__ void k_detect2(const unsigned* __restrict__ ei, long long ei_words,
                          const unsigned* __restrict__ bt, long long bt_words) {
    long long i = 2ll * ((long long)blockIdx.x * blockDim.x + threadIdx.x) + 1;
    unsigned v0 = (i < ei_words) ? ei[i] : 0u;
    unsigned v1 = (i < bt_words) ? bt[i] : 0u;
#pragma unroll
    for (int o = 16; o > 0; o >>= 1) {
        v0 |= __shfl_xor_sync(0xffffffffu, v0, o);
        v1 |= __shfl_xor_sync(0xffffffffu, v1, o);
    }
    if ((threadIdx.x & 31) == 0) {
        if (v0) atomicOr(&g_flags[0], 1);
        if (v1) atomicOr(&g_flags[1], 1);
    }
}

// launch 3: in-degree histogram
__global__ void k_count(const void* __restrict__ ei, long long E) {
    long long e = (long long)blockIdx.x * blockDim.x + threadIdx.x;
    if (e >= E) return;
    int is32 = g_flags[0];
    long long d = fetch_idx(ei, E + e, is32);
    atomicAdd(&g_degi[d], 1);
}

// launch 5: single-block scan -> row_ptr + cursor + dinv
__global__ void k_scan_dinv() {
    __shared__ int part[1024];
    const int CH = (NN + 1023) / 1024;
    int t = threadIdx.x;
    int beg = t * CH, end = min(beg + CH, NN);
    int s = 0;
    for (int i = beg; i < end; i++) {
        int d = g_degi[i];
        g_dinv[i] = rsqrtf((float)d + 1.0f);
        s += d;
    }
    part[t] = s;
    __syncthreads();
    for (int off = 1; off < 1024; off <<= 1) {
        int v = (t >= off) ? part[t - off] : 0;
        __syncthreads();
        part[t] += v;
        __syncthreads();
    }
    int excl = (t == 0) ? 0 : part[t - 1];
    for (int i = beg; i < end; i++) {
        g_rowptr[i] = excl;
        g_cursor[i] = excl;
        excl += g_degi[i];
    }
    if (t == 1023) g_rowptr[NN] = part[1023];
}

// launch 6: CSR fill
__global__ void k_fill(const void* __restrict__ ei, long long E) {
    long long e = (long long)blockIdx.x * blockDim.x + threadIdx.x;
    if (e >= E) return;
    int is32 = g_flags[0];
    int s = (int)fetch_idx(ei, e, is32);
    int d = (int)fetch_idx(ei, E + e, is32);
    int pos = atomicAdd(&g_cursor[d], 1);
    g_csr_src[pos] = s;
    g_csr_w[pos] = g_dinv[s] * g_dinv[d];
}

// ---------------- 3xTF32 tensor-core GEMM v3 (2 blocks/SM) ----------------
// C[M,256] = A[M,256] @ B[256,256]. Block tile 128x128 (grid 391 x 2),
// 8 warps (2m x 4n), warp tile 64x32, BK=8, double-buffered smem,
// operands pre-split to tf32 hi/lo at staging.
__device__ __forceinline__ void split_tf32(float x, uint32_t& hi, uint32_t& lo) {
    asm("cvt.rna.tf32.f32 %0, %1;" : "=r"(hi) : "f"(x));
    float r = x - __uint_as_float(hi);
    asm("cvt.rna.tf32.f32 %0, %1;" : "=r"(lo) : "f"(r));
}

__device__ __forceinline__ void mma8(float* c, const uint32_t* a, const uint32_t* b) {
    asm volatile(
        "mma.sync.aligned.m16n8k8.row.col.f32.tf32.tf32.f32 "
        "{%0,%1,%2,%3}, {%4,%5,%6,%7}, {%8,%9}, {%0,%1,%2,%3};"
        : "+f"(c[0]), "+f"(c[1]), "+f"(c[2]), "+f"(c[3])
        : "r"(a[0]), "r"(a[1]), "r"(a[2]), "r"(a[3]), "r"(b[0]), "r"(b[1]));
}

#define APAD 12    // (12g+t)%32 distinct across a warp
#define BPAD 136   // 136%32==8 -> (8t+g)%32 distinct
#define A_WORDS (2 * 2 * 128 * APAD)           // 6144
#define B_WORDS (2 * 2 * 8 * BPAD)             // 4352
#define GEMM_SMEM ((A_WORDS + B_WORDS) * 4)    // 41984 bytes

#define AS(b, h, r, k) sA[((((b) * 2 + (h)) * 128 + (r)) * APAD) + (k)]
#define BS(b, h, k, n) sB[((((b) * 2 + (h)) * 8 + (k)) * BPAD) + (n)]

__global__ __launch_bounds__(256, 2) void k_gemm3(const float* __restrict__ A,
                                                  const float* __restrict__ B,
                                                  float* __restrict__ C, int M) {
    extern __shared__ uint32_t smem_dyn[];
    uint32_t* sA = smem_dyn;
    uint32_t* sB = smem_dyn + A_WORDS;

    int tid = threadIdx.x, wid = tid >> 5, lane = tid & 31;
    int g = lane >> 2, t = lane & 3;
    int wm = wid & 1, wn = wid >> 1;       // 2(m) x 4(n); warp tile 64x32
    int bm = blockIdx.x * 128;
    int bn = blockIdx.y * 128;

    // staging mapping: A slab 128x8 = 256 float4, B slab 8x128 = 256 float4
    int a_row = tid >> 1;
    int a_kk  = (tid & 1) * 4;
    int b_k   = tid >> 5;
    int b_n   = (tid & 31) * 4;

    long long a_base = (long long)(bm + a_row) * DD + a_kk;
    bool a_ok = (bm + a_row) < M;
    const float4 z4 = make_float4(0.f, 0.f, 0.f, 0.f);

    float acc[4][4][4];
#pragma unroll
    for (int i = 0; i < 4; i++)
#pragma unroll
        for (int j = 0; j < 4; j++)
#pragma unroll
            for (int q = 0; q < 4; q++) acc[i][j][q] = 0.f;

    // prologue: stage slab 0
    {
        float4 pa = a_ok ? *(const float4*)(A + a_base) : z4;
        float4 pb = *(const float4*)(B + (long long)b_k * DD + bn + b_n);
        uint4 h, l;
        split_tf32(pa.x, h.x, l.x); split_tf32(pa.y, h.y, l.y);
        split_tf32(pa.z, h.z, l.z); split_tf32(pa.w, h.w, l.w);
        *(uint4*)&AS(0, 0, a_row, a_kk) = h;
        *(uint4*)&AS(0, 1, a_row, a_kk) = l;
        split_tf32(pb.x, h.x, l.x); split_tf32(pb.y, h.y, l.y);
        split_tf32(pb.z, h.z, l.z); split_tf32(pb.w, h.w, l.w);
        *(uint4*)&BS(0, 0, b_k, b_n) = h;
        *(uint4*)&BS(0, 1, b_k, b_n) = l;
    }
    __syncthreads();

    for (int k0 = 0; k0 < DD / 8; k0++) {
        int cur = k0 & 1, nxt = cur ^ 1;
        bool more = (k0 + 1) < DD / 8;

        float4 pa = z4, pb = z4;
        if (more) {
            int kb = (k0 + 1) * 8;
            pa = a_ok ? *(const float4*)(A + a_base + kb) : z4;
            pb = *(const float4*)(B + (long long)(kb + b_k) * DD + bn + b_n);
        }

        uint32_t bh[4][2], bl[4][2];
#pragma unroll
        for (int j = 0; j < 4; j++) {
            int n = wn * 32 + 8 * j + g;
            bh[j][0] = BS(cur, 0, t, n);     bh[j][1] = BS(cur, 0, t + 4, n);
            bl[j][0] = BS(cur, 1, t, n);     bl[j][1] = BS(cur, 1, t + 4, n);
        }
#pragma unroll
        for (int i = 0; i < 4; i++) {
            int r = wm * 64 + i * 16;
            uint32_t ah[4], al[4];
            ah[0] = AS(cur, 0, r + g, t);      ah[1] = AS(cur, 0, r + g + 8, t);
            ah[2] = AS(cur, 0, r + g, t + 4);  ah[3] = AS(cur, 0, r + g + 8, t + 4);
            al[0] = AS(cur, 1, r + g, t);      al[1] = AS(cur, 1, r + g + 8, t);
            al[2] = AS(cur, 1, r + g, t + 4);  al[3] = AS(cur, 1, r + g + 8, t + 4);
#pragma unroll
            for (int j = 0; j < 4; j++) {
                mma8(acc[i][j], ah, bh[j]);
                mma8(acc[i][j], ah, bl[j]);
                mma8(acc[i][j], al, bh[j]);
            }
        }

        if (more) {
            uint4 h, l;
            split_tf32(pa.x, h.x, l.x); split_tf32(pa.y, h.y, l.y);
            split_tf32(pa.z, h.z, l.z); split_tf32(pa.w, h.w, l.w);
            *(uint4*)&AS(nxt, 0, a_row, a_kk) = h;
            *(uint4*)&AS(nxt, 1, a_row, a_kk) = l;
            split_tf32(pb.x, h.x, l.x); split_tf32(pb.y, h.y, l.y);
            split_tf32(pb.z, h.z, l.z); split_tf32(pb.w, h.w, l.w);
            *(uint4*)&BS(nxt, 0, b_k, b_n) = h;
            *(uint4*)&BS(nxt, 1, b_k, b_n) = l;
        }
        __syncthreads();
    }

#pragma unroll
    for (int i = 0; i < 4; i++)
#pragma unroll
        for (int j = 0; j < 4; j++) {
            int row0 = bm + wm * 64 + i * 16 + g;
            int col  = bn + wn * 32 + 8 * j + 2 * t;
            if (row0 < M) {
                float2 v = {acc[i][j][0], acc[i][j][1]};
                *(float2*)(C + (long long)row0 * DD + col) = v;
            }
            int row1 = row0 + 8;
            if (row1 < M) {
                float2 v = {acc[i][j][2], acc[i][j][3]};
                *(float2*)(C + (long long)row1 * DD + col) = v;
            }
        }
}

// ---------------- fused aggregate: self-loop + CSR gather + bias + relu --------
__global__ __launch_bounds__(256) void k_aggregate(const float* __restrict__ tmp,
                                                   float* __restrict__ out,
                                                   const float* __restrict__ bias) {
    int node = (int)(((long long)blockIdx.x * blockDim.x + threadIdx.x) >> 5);
    int lane = threadIdx.x & 31;
    if (node >= NN) return;

    float di = g_dinv[node];
    float ws = di * di;
    const float4* r = (const float4*)(tmp + (long long)node * DD);
    float4 v0 = r[lane], v1 = r[lane + 32];
    float4 a0 = {v0.x * ws, v0.y * ws, v0.z * ws, v0.w * ws};
    float4 a1 = {v1.x * ws, v1.y * ws, v1.z * ws, v1.w * ws};

    int p = g_rowptr[node], pe = g_rowptr[node + 1];
    // unrolled x2: more outstanding LDG.128s
    for (; p + 2 <= pe; p += 2) {
        int s0 = g_csr_src[p],     s1 = g_csr_src[p + 1];
        float w0 = g_csr_w[p],     w1 = g_csr_w[p + 1];
        const float4* r0 = (const float4*)(tmp + (long long)s0 * DD);
        const float4* r1 = (const float4*)(tmp + (long long)s1 * DD);
        float4 u00 = r0[lane], u01 = r0[lane + 32];
        float4 u10 = r1[lane], u11 = r1[lane + 32];
        a0.x += w0 * u00.x; a0.y += w0 * u00.y; a0.z += w0 * u00.z; a0.w += w0 * u00.w;
        a1.x += w0 * u01.x; a1.y += w0 * u01.y; a1.z += w0 * u01.z; a1.w += w0 * u01.w;
        a0.x += w1 * u10.x; a0.y += w1 * u10.y; a0.z += w1 * u10.z; a0.w += w1 * u10.w;
        a1.x += w1 * u11.x; a1.y += w1 * u11.y; a1.z += w1 * u11.z; a1.w += w1 * u11.w;
    }
    if (p < pe) {
        int s = g_csr_src[p];
        float w = g_csr_w[p];
        const float4* rs = (const float4*)(tmp + (long long)s * DD);
        float4 u0 = rs[lane], u1 = rs[lane + 32];
        a0.x += w * u0.x; a0.y += w * u0.y; a0.z += w * u0.z; a0.w += w * u0.w;
        a1.x += w * u1.x; a1.y += w * u1.y; a1.z += w * u1.z; a1.w += w * u1.w;
    }

    float4 b0 = ((const float4*)bias)[lane];
    float4 b1 = ((const float4*)bias)[lane + 32];
    a0.x = fmaxf(a0.x + b0.x, 0.f); a0.y = fmaxf(a0.y + b0.y, 0.f);
    a0.z = fmaxf(a0.z + b0.z, 0.f); a0.w = fmaxf(a0.w + b0.w, 0.f);
    a1.x = fmaxf(a1.x + b1.x, 0.f); a1.y = fmaxf(a1.y + b1.y, 0.f);
    a1.z = fmaxf(a1.z + b1.z, 0.f); a1.w = fmaxf(a1.w + b1.w, 0.f);

    float4* o = (float4*)(out + (long long)node * DD);
    o[lane] = a0;
    o[lane + 32] = a1;
}

// ---------------- pool: batch is sorted -> segmented per-block sums ------------
__global__ void k_pool2(const float* __restrict__ h, const void* __restrict__ batch) {
    int col = threadIdx.x;
    int n0 = blockIdx.x * 128;
    int n1 = min(n0 + 128, NN);
    int is32 = g_flags[1];
    int cur = (int)fetch_idx(batch, n0, is32);
    float acc = 0.f;
    int cnt = 0;
    for (int n = n0; n < n1; n++) {
        int gid = (int)fetch_idx(batch, n, is32);
        if (gid != cur) {
            atomicAdd(&g_pool[cur * DD + col], acc);
            if (col == 0) atomicAdd(&g_cnt[cur], (float)cnt);
            acc = 0.f; cnt = 0; cur = gid;
        }
        acc += h[(long long)n * DD + col];
        cnt++;
    }
    atomicAdd(&g_pool[cur * DD + col], acc);
    if (col == 0) atomicAdd(&g_cnt[cur], (float)cnt);
}

__global__ void k_fc(const float* __restrict__ Wfc, const float* __restrict__ bfc,
                     float* __restrict__ out) {
    int tt = blockIdx.x * blockDim.x + threadIdx.x;
    if (tt >= GG * DOUT) return;
    int g = tt >> 4, o = tt & 15;
    float inv = 1.0f / fmaxf(g_cnt[g], 1.0f);
    float acc = 0.f;
#pragma unroll 8
    for (int k = 0; k < DD; k++) acc += g_pool[g * DD + k] * Wfc[k * DOUT + o];
    out[tt] = acc * inv + bfc[o];
}

// ---------------- launch ----------------
extern "C" void kernel_launch(void* const* d_in, const int* in_sizes, int n_in,
                              void* d_out, int out_size) {
    const float* x     = (const float*)d_in[0];
    const void*  ei    = d_in[1];
    const void*  batch = d_in[2];
    const float* W1 = (const float*)d_in[3];  const float* b1 = (const float*)d_in[4];
    const float* W2 = (const float*)d_in[5];  const float* b2 = (const float*)d_in[6];
    const float* W3 = (const float*)d_in[7];  const float* b3 = (const float*)d_in[8];
    const float* Wfc = (const float*)d_in[9]; const float* bfc = (const float*)d_in[10];
    float* out = (float*)d_out;

    long long E = in_sizes[1] / 2;

    float *S0, *S1;
    cudaGetSymbolAddress((void**)&S0, g_S0);
    cudaGetSymbolAddress((void**)&S1, g_S1);

    cudaFuncSetAttribute(k_gemm3, cudaFuncAttributeMaxDynamicSharedMemorySize,
                         GEMM_SMEM);

    dim3 gemm_grid((NN + 127) / 128, 2);
    const float* bs[3] = {b1, b2, b3};

    // launch order: GEMM is launch #4 -> gets the ncu -s window
    k_zero<<<(NN + 255) / 256, 256>>>();                                       // 1
    k_detect2<<<(int)((in_sizes[1] / 2 + 255) / 256), 256>>>(
        (const unsigned*)ei, (long long)in_sizes[1],
        (const unsigned*)batch, (long long)in_sizes[2]);                       // 2
    k_count<<<(int)((E + 255) / 256), 256>>>(ei, E);                           // 3
    k_gemm3<<<gemm_grid, 256, GEMM_SMEM>>>(x, W1, S0, NN);                     // 4 (profiled)
    k_scan_dinv<<<1, 1024>>>();                                                // 5
    k_fill<<<(int)((E + 255) / 256), 256>>>(ei, E);                            // 6
    k_aggregate<<<(NN * 32 + 255) / 256, 256>>>(S0, S1, bs[0]);                // 7

    const float* in = S1;
    const float* Ws23[2] = {W2, W3};
    for (int l = 0; l < 2; l++) {
        k_gemm3<<<gemm_grid, 256, GEMM_SMEM>>>(in, Ws23[l], S0, NN);
        k_aggregate<<<(NN * 32 + 255) / 256, 256>>>(S0, S1, bs[l + 1]);
        in = S1;
    }

    k_pool2<<<(NN + 127) / 128, 256>>>(S1, batch);
    k_fc<<<(GG * DOUT + 255) / 256, 256>>>(Wfc, bfc, out);
}